// round 13
// baseline (speedup 1.0000x reference)
#include <cuda_runtime.h>
#include <cstdint>
#include <math.h>

#define D 256
#define MAXN 8192
#define TILE 128
#define CHKB 144                     // smem row bytes: 144 = 9*16 (cp.async-aligned);
                                     // 36 words == 4 mod 32 -> conflict-free ldmatrix
#define ST_BYTES (TILE * CHKB)       // one input stage = 18432 B (K-chunk of 128 s8)
#define STG_ROW 132                  // staged acc row stride (ints)
#define STG_ELEMS (128 * STG_ROW)    // one acc stage = 16896 ints = 67584 B
#define SMEM_TOTAL (4 * ST_BYTES + 2 * STG_ELEMS * 4)   // 208896 B
#define NSM 148

// Scratch (__device__ globals: allocation-free rule)
__device__ int8_t g_znq[MAXN * D];   // normalized rows, s8 (scale 127), 2 MB
__device__ float g_S[MAXN];          // sum_{j!=i} exp(sim_ij - 2)
__device__ float g_pos[MAXN];        // sim[i, partner(i)]

__device__ __forceinline__ uint32_t smem_u32(const void* p) {
    uint32_t a;
    asm("{ .reg .u64 t; cvta.to.shared.u64 t, %1; cvt.u32.u64 %0, t; }"
        : "=r"(a) : "l"(p));
    return a;
}
__device__ __forceinline__ void cp_async16(uint32_t dst, const void* src) {
    asm volatile("cp.async.cg.shared.global [%0], [%1], 16;" :: "r"(dst), "l"(src));
}
#define CP_COMMIT() asm volatile("cp.async.commit_group;" ::: "memory")
#define CP_WAIT(n)  asm volatile("cp.async.wait_group %0;" :: "n"(n) : "memory")

// named barriers: 0/1 = stage empty, 2/3 = stage full, 4 = producer-internal
#define BAR_SYNC(id)   asm volatile("bar.sync %0, 512;"   :: "r"(id) : "memory")
#define BAR_ARRIVE(id) asm volatile("bar.arrive %0, 512;" :: "r"(id) : "memory")
#define BARP()         asm volatile("bar.sync 4, 256;"    ::: "memory")

// ---------------------------------------------------------------------------
// exp(sim-2) from the s32 accumulator: 2^(a*C1 + C0), t in [-5.8, 0.06]
// ---------------------------------------------------------------------------
#define EXP_C1 (1.7886898e-4f)        // 2 * log2(e) / 16129
#define EXP_C0 (-2.8853900817779268f) // -2 * log2(e)
__device__ __forceinline__ float exp2_poly(float t) {
    float fi = rintf(t);
    float f  = t - fi;
    float p  = 1.3333558147e-3f;
    p = fmaf(p, f, 9.6181291071e-3f);
    p = fmaf(p, f, 5.5504108665e-2f);
    p = fmaf(p, f, 2.4022650696e-1f);
    p = fmaf(p, f, 6.9314718056e-1f);
    p = fmaf(p, f, 1.0f);
    int i = (int)fi;
    return p * __int_as_float((i + 127) << 23);
}

// ---------------------------------------------------------------------------
// Kernel 1: normalize rows -> s8 (scale 127). Warp per row, 8 rows/block.
// ---------------------------------------------------------------------------
__global__ __launch_bounds__(256)
void k_normalize(const float* __restrict__ zi,
                 const float* __restrict__ zj, int B) {
    const int w   = threadIdx.x >> 5;
    const int lid = threadIdx.x & 31;
    const int row = blockIdx.x * 8 + w;
    const float* src = (row < B) ? (zi + (size_t)row * D)
                                 : (zj + (size_t)(row - B) * D);
    float4 v0 = *reinterpret_cast<const float4*>(src + lid * 8);
    float4 v1 = *reinterpret_cast<const float4*>(src + lid * 8 + 4);
    float s = v0.x*v0.x + v0.y*v0.y + v0.z*v0.z + v0.w*v0.w
            + v1.x*v1.x + v1.y*v1.y + v1.z*v1.z + v1.w*v1.w;
    #pragma unroll
    for (int o = 16; o > 0; o >>= 1) s += __shfl_xor_sync(0xffffffffu, s, o);
    float q = 127.0f / fmaxf(sqrtf(s), 1e-8f);

    int i0 = __float2int_rn(v0.x * q), i1 = __float2int_rn(v0.y * q);
    int i2 = __float2int_rn(v0.z * q), i3 = __float2int_rn(v0.w * q);
    int i4 = __float2int_rn(v1.x * q), i5 = __float2int_rn(v1.y * q);
    int i6 = __float2int_rn(v1.z * q), i7 = __float2int_rn(v1.w * q);
    uint2 pk;
    pk.x = (uint32_t)(i0 & 255) | ((uint32_t)(i1 & 255) << 8) |
           ((uint32_t)(i2 & 255) << 16) | ((uint32_t)(i3 & 255) << 24);
    pk.y = (uint32_t)(i4 & 255) | ((uint32_t)(i5 & 255) << 8) |
           ((uint32_t)(i6 & 255) << 16) | ((uint32_t)(i7 & 255) << 24);
    *reinterpret_cast<uint2*>(&g_znq[(size_t)row * D + lid * 8]) = pk;
    if (lid == 0) { g_S[row] = 0.0f; g_pos[row] = 0.0f; }
}

// ---------------------------------------------------------------------------
// Kernel 2: persistent warp-specialized GEMM+epilogue. 148 CTAs x 512 thr.
// Warps 0-7 (producers): cp.async + ldsm + IMMA, stage s32 acc to smem ring.
// Warps 8-15 (consumers): exp/reduce/atomic epilogue from the staged acc.
// Named-barrier double-buffer handshake; next tile's loads overlap MMA.
// ---------------------------------------------------------------------------
__global__ __launch_bounds__(512, 1)
void k_simgemm_ws(int B, int NT) {
    extern __shared__ uint8_t smem[];
    uint8_t* As = smem;                          // 2 input stages
    uint8_t* Bs = smem + 2 * ST_BYTES;           // 2 input stages
    int* stage  = reinterpret_cast<int*>(smem + 4 * ST_BYTES);  // 2 acc stages

    const int tid = threadIdx.x;
    const int wid = tid >> 5, lid = tid & 31;

    auto decode = [](int t, int& by, int& bx) {
        by = (int)((sqrtf(8.0f * (float)t + 1.0f) - 1.0f) * 0.5f);
        while ((by + 1) * (by + 2) / 2 <= t) by++;
        while (by * (by + 1) / 2 > t) by--;
        bx = t - by * (by + 1) / 2;
    };

    if (wid < 8) {
        // =================== PRODUCERS (threads 0..255) ====================
        const int warp_m = wid & 3;
        const int warp_n = wid >> 2;
        const int qrow = lid >> 2, qcol = lid & 3;

        auto issue_chunk = [&](int r0, int c0, int ch) {
            #pragma unroll
            for (int q = 0; q < 4; q++) {
                int li  = tid + q * 256;            // 0..1023
                int row = li >> 3;                  // 0..127
                int seg = (li & 7) << 4;            // 0..112 bytes
                uint32_t dstA = smem_u32(&As[ch * ST_BYTES + row * CHKB + seg]);
                uint32_t dstB = smem_u32(&Bs[ch * ST_BYTES + row * CHKB + seg]);
                cp_async16(dstA, &g_znq[(size_t)(r0 + row) * D + ch * 128 + seg]);
                cp_async16(dstB, &g_znq[(size_t)(c0 + row) * D + ch * 128 + seg]);
            }
            CP_COMMIT();
        };

        // ldmatrix base addresses (input stage 0), byte offsets
        uint32_t aAddr[2];
        #pragma unroll
        for (int mf = 0; mf < 2; mf++) {
            int row  = warp_m * 32 + mf * 16 + (lid & 15);
            int colb = (lid >> 4) << 4;
            aAddr[mf] = smem_u32(&As[row * CHKB + colb]);
        }
        uint32_t bAddr[4];
        #pragma unroll
        for (int nq = 0; nq < 4; nq++) {
            int row  = warp_n * 64 + nq * 16 + ((lid >> 4) << 3) + (lid & 7);
            int colb = (lid & 8) << 1;
            bAddr[nq] = smem_u32(&Bs[row * CHKB + colb]);
        }

        int t = blockIdx.x;
        int by, bx; decode(t, by, bx);
        int r0 = by * TILE, c0 = bx * TILE;
        issue_chunk(r0, c0, 0);
        issue_chunk(r0, c0, 1);

        for (int k = 0; t < NT; k++) {
            const int tn = t + gridDim.x;
            const bool have_next = (tn < NT);
            int rn = 0, cn = 0;
            if (have_next) { int byn, bxn; decode(tn, byn, bxn); rn = byn * TILE; cn = bxn * TILE; }

            int acc[2][8][4];
            #pragma unroll
            for (int i = 0; i < 2; i++)
                #pragma unroll
                for (int j = 0; j < 8; j++)
                    #pragma unroll
                    for (int e = 0; e < 4; e++) acc[i][j][e] = 0;

            #pragma unroll
            for (int ch = 0; ch < 2; ch++) {
                if (ch == 0) CP_WAIT(1); else CP_WAIT(0);
                BARP();                               // chunk ch resident, all producers
                if (ch == 1 && have_next) issue_chunk(rn, cn, 0);  // buf0 free
                const uint32_t cb = (uint32_t)ch * ST_BYTES;
                #pragma unroll
                for (int ks = 0; ks < 4; ks++) {
                    const uint32_t kb = cb + ks * 32;
                    uint32_t a[2][4], b[4][4];
                    #pragma unroll
                    for (int mf = 0; mf < 2; mf++)
                        asm volatile("ldmatrix.sync.aligned.m8n8.x4.shared.b16 {%0,%1,%2,%3}, [%4];"
                                     : "=r"(a[mf][0]), "=r"(a[mf][1]), "=r"(a[mf][2]), "=r"(a[mf][3])
                                     : "r"(aAddr[mf] + kb));
                    #pragma unroll
                    for (int nq = 0; nq < 4; nq++)
                        asm volatile("ldmatrix.sync.aligned.m8n8.x4.shared.b16 {%0,%1,%2,%3}, [%4];"
                                     : "=r"(b[nq][0]), "=r"(b[nq][1]), "=r"(b[nq][2]), "=r"(b[nq][3])
                                     : "r"(bAddr[nq] + kb));
                    #pragma unroll
                    for (int mf = 0; mf < 2; mf++)
                        #pragma unroll
                        for (int nf = 0; nf < 8; nf++) {
                            const int nq = nf >> 1, base = (nf & 1) * 2;
                            asm volatile(
                                "mma.sync.aligned.m16n8k32.row.col.s32.s8.s8.s32 "
                                "{%0,%1,%2,%3}, {%4,%5,%6,%7}, {%8,%9}, {%0,%1,%2,%3};"
                                : "+r"(acc[mf][nf][0]), "+r"(acc[mf][nf][1]),
                                  "+r"(acc[mf][nf][2]), "+r"(acc[mf][nf][3])
                                : "r"(a[mf][0]), "r"(a[mf][1]), "r"(a[mf][2]), "r"(a[mf][3]),
                                  "r"(b[nq][base]), "r"(b[nq][base + 1]));
                        }
                }
            }
            BARP();                                   // all done reading buf1
            if (have_next) issue_chunk(rn, cn, 1);

            // hand accumulators to consumers
            const int slot = k & 1;
            if (k >= 2) BAR_SYNC(slot);               // stage[slot] empty
            int* sg = stage + slot * STG_ELEMS;
            #pragma unroll
            for (int mf = 0; mf < 2; mf++)
                #pragma unroll
                for (int sub = 0; sub < 2; sub++) {
                    const int row = warp_m * 32 + mf * 16 + sub * 8 + qrow;
                    #pragma unroll
                    for (int nf = 0; nf < 8; nf++) {
                        int2 v = make_int2(acc[mf][nf][sub * 2], acc[mf][nf][sub * 2 + 1]);
                        *reinterpret_cast<int2*>(
                            &sg[row * STG_ROW + warp_n * 64 + nf * 8 + qcol * 2]) = v;
                    }
                }
            asm volatile("membar.cta;" ::: "memory");
            BAR_ARRIVE(2 + slot);                     // stage[slot] full
            t = tn;
        }
    } else {
        // =================== CONSUMERS (threads 256..511) ==================
        const int cw = wid - 8;
        const int warp_m = cw & 3;
        const int warp_n = cw >> 2;
        const int qrow = lid >> 2, qcol = lid & 3;
        const float SC = 2.0f / 16129.0f;

        int t = blockIdx.x;
        for (int k = 0; t < NT; k++, t += gridDim.x) {
            int by, bx; decode(t, by, bx);
            const int r0 = by * TILE, c0 = bx * TILE;
            const bool diag = (by == bx);
            const bool has_pos = (by == bx + (B / TILE));
            const int slot = k & 1;
            BAR_SYNC(2 + slot);                       // stage[slot] full
            const int* sg = stage + slot * STG_ELEMS;

            float rs[4] = {0.f, 0.f, 0.f, 0.f};
            float cs[8][2];
            #pragma unroll
            for (int nf = 0; nf < 8; nf++) { cs[nf][0] = 0.f; cs[nf][1] = 0.f; }

            #pragma unroll
            for (int mf = 0; mf < 2; mf++) {
                #pragma unroll
                for (int sub = 0; sub < 2; sub++) {
                    const int r = r0 + warp_m * 32 + mf * 16 + sub * 8 + qrow;
                    const int partner = (r < B) ? (r + B) : (r - B);
                    const int rowoff = (warp_m * 32 + mf * 16 + sub * 8 + qrow) * STG_ROW;
                    #pragma unroll
                    for (int nf = 0; nf < 8; nf++) {
                        int2 av = *reinterpret_cast<const int2*>(
                            &sg[rowoff + warp_n * 64 + nf * 8 + qcol * 2]);
                        #pragma unroll
                        for (int e = 0; e < 2; e++) {
                            const int a = (e == 0) ? av.x : av.y;
                            const int c = c0 + warp_n * 64 + nf * 8 + qcol * 2 + e;
                            float ex = exp2_poly(fmaf((float)a, EXP_C1, EXP_C0));
                            if (diag && c == r) ex = 0.0f;
                            rs[mf * 2 + sub] += ex;
                            if (!diag) cs[nf][e] += ex;
                            if (has_pos && c == partner) {
                                const float sim = SC * (float)a;
                                g_pos[r] = sim; g_pos[c] = sim;
                            }
                        }
                    }
                }
            }
            BAR_ARRIVE(slot);                         // stage reads done -> empty

            #pragma unroll
            for (int i = 0; i < 4; i++) {
                rs[i] += __shfl_xor_sync(0xffffffffu, rs[i], 1);
                rs[i] += __shfl_xor_sync(0xffffffffu, rs[i], 2);
            }
            if (qcol == 0) {
                #pragma unroll
                for (int mf = 0; mf < 2; mf++)
                    #pragma unroll
                    for (int sub = 0; sub < 2; sub++) {
                        const int r = r0 + warp_m * 32 + mf * 16 + sub * 8 + qrow;
                        atomicAdd(&g_S[r], rs[mf * 2 + sub]);
                    }
            }
            if (!diag) {
                #pragma unroll
                for (int nf = 0; nf < 8; nf++) {
                    #pragma unroll
                    for (int e = 0; e < 2; e++) {
                        float v = cs[nf][e];
                        v += __shfl_xor_sync(0xffffffffu, v, 4);
                        v += __shfl_xor_sync(0xffffffffu, v, 8);
                        v += __shfl_xor_sync(0xffffffffu, v, 16);
                        if (lid < 4) {
                            const int c = c0 + warp_n * 64 + nf * 8 + qcol * 2 + e;
                            atomicAdd(&g_S[c], v);
                        }
                    }
                }
            }
        }
    }
}

// ---------------------------------------------------------------------------
// Kernel 3: loss = (1/N) * sum_i (2 + log(S_i) - pos_i)
// ---------------------------------------------------------------------------
__global__ void k_final(float* __restrict__ out, int Nn) {
    int t = threadIdx.x;
    float s = 0.0f;
    for (int i = t; i < Nn; i += 1024)
        s += 2.0f + logf(g_S[i]) - g_pos[i];
    #pragma unroll
    for (int o = 16; o > 0; o >>= 1) s += __shfl_xor_sync(0xffffffffu, s, o);
    __shared__ float ws[32];
    if ((t & 31) == 0) ws[t >> 5] = s;
    __syncthreads();
    if (t < 32) {
        float x = ws[t];
        #pragma unroll
        for (int o = 16; o > 0; o >>= 1) x += __shfl_xor_sync(0xffffffffu, x, o);
        if (t == 0) out[0] = x / (float)Nn;
    }
}

// ---------------------------------------------------------------------------
extern "C" void kernel_launch(void* const* d_in, const int* in_sizes, int n_in,
                              void* d_out, int out_size) {
    const float* zi = (const float*)d_in[0];
    const float* zj = (const float*)d_in[1];
    int B  = in_sizes[0] / D;   // 4096
    int Nn = 2 * B;             // 8192

    cudaFuncSetAttribute(k_simgemm_ws,
                         cudaFuncAttributeMaxDynamicSharedMemorySize, SMEM_TOTAL);

    k_normalize<<<Nn / 8, 256>>>(zi, zj, B);
    const int ntiles = Nn / TILE;                  // 64
    const int NT = ntiles * (ntiles + 1) / 2;      // 2080
    k_simgemm_ws<<<NSM, 512, SMEM_TOTAL>>>(B, NT);
    k_final<<<1, 1024>>>((float*)d_out, Nn);
}

// round 14
// speedup vs baseline: 1.2981x; 1.2981x over previous
#include <cuda_runtime.h>
#include <cstdint>
#include <math.h>

#define D 256
#define MAXN 8192
#define TILE 128
#define CHKB 144                     // smem row bytes: 144 = 9*16 (cp.async-aligned);
                                     // 36 words == 4 mod 32 -> conflict-free ldmatrix
#define ST_BYTES (TILE * CHKB)       // one stage = 18432 B (K-chunk of 128 s8)
#define NCTA 296                     // persistent: 2 CTAs per SM

// Scratch (__device__ globals: allocation-free rule)
__device__ int8_t g_znq[MAXN * D];   // normalized rows, s8 (scale 127), 2 MB
__device__ float g_S[MAXN];          // sum_{j!=i} exp(sim_ij - 2)
__device__ float g_pos[MAXN];        // sim[i, partner(i)]

__device__ __forceinline__ uint32_t smem_u32(const void* p) {
    uint32_t a;
    asm("{ .reg .u64 t; cvta.to.shared.u64 t, %1; cvt.u32.u64 %0, t; }"
        : "=r"(a) : "l"(p));
    return a;
}
__device__ __forceinline__ void cp_async16(uint32_t dst, const void* src) {
    asm volatile("cp.async.cg.shared.global [%0], [%1], 16;" :: "r"(dst), "l"(src));
}
#define CP_COMMIT() asm volatile("cp.async.commit_group;" ::: "memory")
#define CP_WAIT(n)  asm volatile("cp.async.wait_group %0;" :: "n"(n) : "memory")

// ---------------------------------------------------------------------------
// exp(sim-2) from the s32 accumulator: 2^(a*C1 + C0), t in [-5.83, 0.06]
// ---------------------------------------------------------------------------
#define EXP_C1 (1.7886898e-4f)        // 2 * log2(e) / 16129
#define EXP_C0 (-2.8853900817779268f) // -2 * log2(e)
__device__ __forceinline__ float exp2_poly(float t) {
    float fi = rintf(t);
    float f  = t - fi;
    float p  = 1.3333558147e-3f;
    p = fmaf(p, f, 9.6181291071e-3f);
    p = fmaf(p, f, 5.5504108665e-2f);
    p = fmaf(p, f, 2.4022650696e-1f);
    p = fmaf(p, f, 6.9314718056e-1f);
    p = fmaf(p, f, 1.0f);
    int i = (int)fi;
    return p * __int_as_float((i + 127) << 23);
}

// ---------------------------------------------------------------------------
// Kernel 1: normalize rows -> s8 (scale 127). Warp per row, 8 rows/block.
// ---------------------------------------------------------------------------
__global__ __launch_bounds__(256)
void k_normalize(const float* __restrict__ zi,
                 const float* __restrict__ zj, int B) {
    const int w   = threadIdx.x >> 5;
    const int lid = threadIdx.x & 31;
    const int row = blockIdx.x * 8 + w;
    const float* src = (row < B) ? (zi + (size_t)row * D)
                                 : (zj + (size_t)(row - B) * D);
    float4 v0 = *reinterpret_cast<const float4*>(src + lid * 8);
    float4 v1 = *reinterpret_cast<const float4*>(src + lid * 8 + 4);
    float s = v0.x*v0.x + v0.y*v0.y + v0.z*v0.z + v0.w*v0.w
            + v1.x*v1.x + v1.y*v1.y + v1.z*v1.z + v1.w*v1.w;
    #pragma unroll
    for (int o = 16; o > 0; o >>= 1) s += __shfl_xor_sync(0xffffffffu, s, o);
    float q = 127.0f / fmaxf(sqrtf(s), 1e-8f);

    int i0 = __float2int_rn(v0.x * q), i1 = __float2int_rn(v0.y * q);
    int i2 = __float2int_rn(v0.z * q), i3 = __float2int_rn(v0.w * q);
    int i4 = __float2int_rn(v1.x * q), i5 = __float2int_rn(v1.y * q);
    int i6 = __float2int_rn(v1.z * q), i7 = __float2int_rn(v1.w * q);
    uint2 pk;
    pk.x = (uint32_t)(i0 & 255) | ((uint32_t)(i1 & 255) << 8) |
           ((uint32_t)(i2 & 255) << 16) | ((uint32_t)(i3 & 255) << 24);
    pk.y = (uint32_t)(i4 & 255) | ((uint32_t)(i5 & 255) << 8) |
           ((uint32_t)(i6 & 255) << 16) | ((uint32_t)(i7 & 255) << 24);
    *reinterpret_cast<uint2*>(&g_znq[(size_t)row * D + lid * 8]) = pk;
    if (lid == 0) { g_S[row] = 0.0f; g_pos[row] = 0.0f; }
}

// ---------------------------------------------------------------------------
// Kernel 2: persistent lower-triangle 128x128 tiles, s8 mma.sync.m16n8k32.
// 296 CTAs (2/SM) stride the 2080 tiles. Cross-tile prefetch: next tile's
// two 128-B K-chunks are issued as soon as the current tile's MMAs finish
// reading the buffers, so loads fly during the epilogue and the next tile's
// CP_WAIT returns immediately. 72KB smem, 128-reg budget (no spills; occ=3
// regressed in R11, warp-specialization regressed in R13).
// ---------------------------------------------------------------------------
__global__ __launch_bounds__(256, 2)
void k_simgemm_sym(int B, int NT) {
    extern __shared__ uint8_t smem[];
    uint8_t* As = smem;                      // 2 stages
    uint8_t* Bs = smem + 2 * ST_BYTES;       // 2 stages

    const int tid = threadIdx.x;
    const int wid = tid >> 5, lid = tid & 31;
    const int warp_m = wid & 3;
    const int warp_n = wid >> 2;
    const int qrow = lid >> 2, qcol = lid & 3;
    const float SC = 2.0f / 16129.0f;        // 2 / 127^2 (for pos sim values)

    auto decode = [](int t, int& by, int& bx) {
        by = (int)((sqrtf(8.0f * (float)t + 1.0f) - 1.0f) * 0.5f);
        while ((by + 1) * (by + 2) / 2 <= t) by++;
        while (by * (by + 1) / 2 > t) by--;
        bx = t - by * (by + 1) / 2;
    };

    auto issue_chunk = [&](int r0, int c0, int ch) {
        #pragma unroll
        for (int q = 0; q < 4; q++) {
            int li  = tid + q * 256;            // 0..1023
            int row = li >> 3;                  // 0..127
            int seg = (li & 7) << 4;            // 0..112 bytes
            uint32_t dstA = smem_u32(&As[ch * ST_BYTES + row * CHKB + seg]);
            uint32_t dstB = smem_u32(&Bs[ch * ST_BYTES + row * CHKB + seg]);
            cp_async16(dstA, &g_znq[(size_t)(r0 + row) * D + ch * 128 + seg]);
            cp_async16(dstB, &g_znq[(size_t)(c0 + row) * D + ch * 128 + seg]);
        }
        CP_COMMIT();
    };

    // per-lane ldmatrix base addresses (stage 0), byte offsets
    uint32_t aAddr[2];
    #pragma unroll
    for (int mf = 0; mf < 2; mf++) {
        int row  = warp_m * 32 + mf * 16 + (lid & 15);
        int colb = (lid >> 4) << 4;             // 0 or 16
        aAddr[mf] = smem_u32(&As[row * CHKB + colb]);
    }
    uint32_t bAddr[4];
    #pragma unroll
    for (int nq = 0; nq < 4; nq++) {
        int row  = warp_n * 64 + nq * 16 + ((lid >> 4) << 3) + (lid & 7);
        int colb = (lid & 8) << 1;              // 0 or 16
        bAddr[nq] = smem_u32(&Bs[row * CHKB + colb]);
    }

    int t = blockIdx.x;
    if (t < NT) {
        int by, bx; decode(t, by, bx);
        issue_chunk(by * TILE, bx * TILE, 0);
        issue_chunk(by * TILE, bx * TILE, 1);
    }

    while (t < NT) {
        int by, bx; decode(t, by, bx);
        const int r0 = by * TILE, c0 = bx * TILE;
        const bool diag = (by == bx);
        const bool has_pos = (by == bx + (B / TILE));

        const int tn = t + NCTA;
        const bool have_next = (tn < NT);
        int rn = 0, cn = 0;
        if (have_next) { int byn, bxn; decode(tn, byn, bxn); rn = byn * TILE; cn = bxn * TILE; }

        int acc[2][8][4];
        #pragma unroll
        for (int i = 0; i < 2; i++)
            #pragma unroll
            for (int j = 0; j < 8; j++)
                #pragma unroll
                for (int e = 0; e < 4; e++) acc[i][j][e] = 0;

        #pragma unroll
        for (int ch = 0; ch < 2; ch++) {
            if (ch == 0) CP_WAIT(1); else CP_WAIT(0);
            __syncthreads();
            const uint32_t cb = (uint32_t)ch * ST_BYTES;
            #pragma unroll
            for (int ks = 0; ks < 4; ks++) {          // 4 k-steps of 32 per chunk
                const uint32_t kb = cb + ks * 32;
                uint32_t a[2][4], b[4][4];
                #pragma unroll
                for (int mf = 0; mf < 2; mf++)
                    asm volatile("ldmatrix.sync.aligned.m8n8.x4.shared.b16 {%0,%1,%2,%3}, [%4];"
                                 : "=r"(a[mf][0]), "=r"(a[mf][1]), "=r"(a[mf][2]), "=r"(a[mf][3])
                                 : "r"(aAddr[mf] + kb));
                #pragma unroll
                for (int nq = 0; nq < 4; nq++)
                    asm volatile("ldmatrix.sync.aligned.m8n8.x4.shared.b16 {%0,%1,%2,%3}, [%4];"
                                 : "=r"(b[nq][0]), "=r"(b[nq][1]), "=r"(b[nq][2]), "=r"(b[nq][3])
                                 : "r"(bAddr[nq] + kb));
                #pragma unroll
                for (int mf = 0; mf < 2; mf++)
                    #pragma unroll
                    for (int nf = 0; nf < 8; nf++) {
                        const int nq = nf >> 1, base = (nf & 1) * 2;
                        asm volatile(
                            "mma.sync.aligned.m16n8k32.row.col.s32.s8.s8.s32 "
                            "{%0,%1,%2,%3}, {%4,%5,%6,%7}, {%8,%9}, {%0,%1,%2,%3};"
                            : "+r"(acc[mf][nf][0]), "+r"(acc[mf][nf][1]),
                              "+r"(acc[mf][nf][2]), "+r"(acc[mf][nf][3])
                            : "r"(a[mf][0]), "r"(a[mf][1]), "r"(a[mf][2]), "r"(a[mf][3]),
                              "r"(b[nq][base]), "r"(b[nq][base + 1]));
                    }
            }
        }
        __syncthreads();           // all warps done reading both buffers
        if (have_next) {           // prefetch next tile; flies during epilogue
            issue_chunk(rn, cn, 0);
            issue_chunk(rn, cn, 1);
        }

        // -------------------------------------------------------------------
        // Epilogue. exp(sim-2) = 2^(acc*C1 + C0). Off-diag: row sums AND
        // column sums (mirror tile). Diag: row sums only, mask c==r.
        // -------------------------------------------------------------------
        float rs[4] = {0.f, 0.f, 0.f, 0.f};
        float cs[8][2];
        #pragma unroll
        for (int nf = 0; nf < 8; nf++) { cs[nf][0] = 0.f; cs[nf][1] = 0.f; }

        #pragma unroll
        for (int mf = 0; mf < 2; mf++) {
            #pragma unroll
            for (int sub = 0; sub < 2; sub++) {
                const int r = r0 + warp_m * 32 + mf * 16 + sub * 8 + qrow;
                const int partner = (r < B) ? (r + B) : (r - B);
                #pragma unroll
                for (int nf = 0; nf < 8; nf++) {
                    #pragma unroll
                    for (int e = 0; e < 2; e++) {
                        const int c = c0 + warp_n * 64 + nf * 8 + qcol * 2 + e;
                        const int av = acc[mf][nf][sub * 2 + e];
                        float ex = exp2_poly(fmaf((float)av, EXP_C1, EXP_C0));
                        if (diag && c == r) ex = 0.0f;
                        rs[mf * 2 + sub] += ex;
                        if (!diag) cs[nf][e] += ex;
                        if (has_pos && c == partner) {
                            const float sim = SC * (float)av;
                            g_pos[r] = sim; g_pos[c] = sim;
                        }
                    }
                }
            }
        }

        #pragma unroll
        for (int i = 0; i < 4; i++) {
            rs[i] += __shfl_xor_sync(0xffffffffu, rs[i], 1);
            rs[i] += __shfl_xor_sync(0xffffffffu, rs[i], 2);
        }
        if (qcol == 0) {
            #pragma unroll
            for (int mf = 0; mf < 2; mf++)
                #pragma unroll
                for (int sub = 0; sub < 2; sub++) {
                    const int r = r0 + warp_m * 32 + mf * 16 + sub * 8 + qrow;
                    atomicAdd(&g_S[r], rs[mf * 2 + sub]);
                }
        }
        if (!diag) {
            #pragma unroll
            for (int nf = 0; nf < 8; nf++) {
                #pragma unroll
                for (int e = 0; e < 2; e++) {
                    float v = cs[nf][e];
                    v += __shfl_xor_sync(0xffffffffu, v, 4);
                    v += __shfl_xor_sync(0xffffffffu, v, 8);
                    v += __shfl_xor_sync(0xffffffffu, v, 16);
                    if (lid < 4) {
                        const int c = c0 + warp_n * 64 + nf * 8 + qcol * 2 + e;
                        atomicAdd(&g_S[c], v);
                    }
                }
            }
        }
        t = tn;
    }
}

// ---------------------------------------------------------------------------
// Kernel 3: loss = (1/N) * sum_i (2 + log(S_i) - pos_i)
// ---------------------------------------------------------------------------
__global__ void k_final(float* __restrict__ out, int Nn) {
    int t = threadIdx.x;
    float s = 0.0f;
    for (int i = t; i < Nn; i += 1024)
        s += 2.0f + logf(g_S[i]) - g_pos[i];
    #pragma unroll
    for (int o = 16; o > 0; o >>= 1) s += __shfl_xor_sync(0xffffffffu, s, o);
    __shared__ float ws[32];
    if ((t & 31) == 0) ws[t >> 5] = s;
    __syncthreads();
    if (t < 32) {
        float x = ws[t];
        #pragma unroll
        for (int o = 16; o > 0; o >>= 1) x += __shfl_xor_sync(0xffffffffu, x, o);
        if (t == 0) out[0] = x / (float)Nn;
    }
}

// ---------------------------------------------------------------------------
extern "C" void kernel_launch(void* const* d_in, const int* in_sizes, int n_in,
                              void* d_out, int out_size) {
    const float* zi = (const float*)d_in[0];
    const float* zj = (const float*)d_in[1];
    int B  = in_sizes[0] / D;   // 4096
    int Nn = 2 * B;             // 8192

    const int smem_bytes = 4 * ST_BYTES;   // 73728
    cudaFuncSetAttribute(k_simgemm_sym,
                         cudaFuncAttributeMaxDynamicSharedMemorySize, smem_bytes);

    k_normalize<<<Nn / 8, 256>>>(zi, zj, B);
    const int ntiles = Nn / TILE;                  // 64
    const int NT = ntiles * (ntiles + 1) / 2;      // 2080
    k_simgemm_sym<<<NCTA, 256, smem_bytes>>>(B, NT);
    k_final<<<1, 1024>>>((float*)d_out, Nn);
}

// round 15
// speedup vs baseline: 1.4571x; 1.1225x over previous
#include <cuda_runtime.h>
#include <cstdint>
#include <math.h>

#define D 256
#define MAXN 8192
#define TILE 128
#define CHKB 144                     // smem row bytes: 144 = 9*16 (cp.async-aligned);
                                     // 36 words == 4 mod 32 -> conflict-free ldmatrix
#define ST_BYTES (TILE * CHKB)       // one stage = 18432 B (K-chunk of 128 s8)

// Scratch (__device__ globals: allocation-free rule)
__device__ int8_t g_znq[MAXN * D];   // normalized rows, s8 (scale 127), 2 MB
__device__ float g_S[MAXN];          // sum_{j!=i} exp(sim_ij - 2)
__device__ float g_pos[MAXN];        // sim[i, partner(i)]

__device__ __forceinline__ uint32_t smem_u32(const void* p) {
    uint32_t a;
    asm("{ .reg .u64 t; cvta.to.shared.u64 t, %1; cvt.u32.u64 %0, t; }"
        : "=r"(a) : "l"(p));
    return a;
}
__device__ __forceinline__ void cp_async16(uint32_t dst, const void* src) {
    asm volatile("cp.async.cg.shared.global [%0], [%1], 16;" :: "r"(dst), "l"(src));
}
#define CP_COMMIT() asm volatile("cp.async.commit_group;" ::: "memory")
#define CP_WAIT(n)  asm volatile("cp.async.wait_group %0;" :: "n"(n) : "memory")

// ---------------------------------------------------------------------------
// exp(sim-2) from the s32 accumulator via the MUFU pipe:
//   exp(sim-2) = 2^(a*C1 + C0);  1 cvt + 1 FMA + 1 ex2.approx per element.
//   MUFU.EX2 rel err ~2^-22 — invisible next to the s8 quantization (2e-5).
// ---------------------------------------------------------------------------
#define EXP_C1 (1.7886898e-4f)        // 2 * log2(e) / 16129
#define EXP_C0 (-2.8853900817779268f) // -2 * log2(e)
__device__ __forceinline__ float exp2_mufu(float t) {
    float r;
    asm("ex2.approx.f32 %0, %1;" : "=f"(r) : "f"(t));
    return r;
}

// ---------------------------------------------------------------------------
// Kernel 1: normalize rows -> s8 (scale 127). Warp per row, 8 rows/block.
// ---------------------------------------------------------------------------
__global__ __launch_bounds__(256)
void k_normalize(const float* __restrict__ zi,
                 const float* __restrict__ zj, int B) {
    const int w   = threadIdx.x >> 5;
    const int lid = threadIdx.x & 31;
    const int row = blockIdx.x * 8 + w;
    const float* src = (row < B) ? (zi + (size_t)row * D)
                                 : (zj + (size_t)(row - B) * D);
    float4 v0 = *reinterpret_cast<const float4*>(src + lid * 8);
    float4 v1 = *reinterpret_cast<const float4*>(src + lid * 8 + 4);
    float s = v0.x*v0.x + v0.y*v0.y + v0.z*v0.z + v0.w*v0.w
            + v1.x*v1.x + v1.y*v1.y + v1.z*v1.z + v1.w*v1.w;
    #pragma unroll
    for (int o = 16; o > 0; o >>= 1) s += __shfl_xor_sync(0xffffffffu, s, o);
    float q = 127.0f / fmaxf(sqrtf(s), 1e-8f);

    int i0 = __float2int_rn(v0.x * q), i1 = __float2int_rn(v0.y * q);
    int i2 = __float2int_rn(v0.z * q), i3 = __float2int_rn(v0.w * q);
    int i4 = __float2int_rn(v1.x * q), i5 = __float2int_rn(v1.y * q);
    int i6 = __float2int_rn(v1.z * q), i7 = __float2int_rn(v1.w * q);
    uint2 pk;
    pk.x = (uint32_t)(i0 & 255) | ((uint32_t)(i1 & 255) << 8) |
           ((uint32_t)(i2 & 255) << 16) | ((uint32_t)(i3 & 255) << 24);
    pk.y = (uint32_t)(i4 & 255) | ((uint32_t)(i5 & 255) << 8) |
           ((uint32_t)(i6 & 255) << 16) | ((uint32_t)(i7 & 255) << 24);
    *reinterpret_cast<uint2*>(&g_znq[(size_t)row * D + lid * 8]) = pk;
    if (lid == 0) { g_S[row] = 0.0f; g_pos[row] = 0.0f; }
}

// ---------------------------------------------------------------------------
// Kernel 2: lower-triangle 128x128 tiles (2080 CTAs), s8 mma.sync.m16n8k32.
// K=256 as 2 chunks of 128 B, cp.async prefetched; 72KB smem, 2 CTAs/SM.
// Epilogue exp on MUFU (ex2.approx) -> ~3 issue slots/element instead of ~12,
// so the epilogue phase compresses and overlaps the co-resident CTA's MMA.
// ---------------------------------------------------------------------------
__global__ __launch_bounds__(256, 2)
void k_simgemm_sym(int Nn, int B) {
    extern __shared__ uint8_t smem[];
    uint8_t* As = smem;                      // 2 stages
    uint8_t* Bs = smem + 2 * ST_BYTES;       // 2 stages

    // decode lower-triangle tile (by >= bx)
    int idx = blockIdx.x;
    int by = (int)((sqrtf(8.0f * (float)idx + 1.0f) - 1.0f) * 0.5f);
    while ((by + 1) * (by + 2) / 2 <= idx) by++;
    while (by * (by + 1) / 2 > idx) by--;
    int bx = idx - by * (by + 1) / 2;
    const int r0 = by * TILE, c0 = bx * TILE;
    const bool diag = (by == bx);

    const int tid = threadIdx.x;
    const int wid = tid >> 5, lid = tid & 31;

    // chunk loader: 128 rows x 128 B per matrix = 1024 x 16B -> 4/thread each
    auto issue_chunk = [&](int ch) {
        #pragma unroll
        for (int q = 0; q < 4; q++) {
            int li  = tid + q * 256;            // 0..1023
            int row = li >> 3;                  // 0..127
            int seg = (li & 7) << 4;            // 0..112 bytes
            uint32_t dstA = smem_u32(&As[ch * ST_BYTES + row * CHKB + seg]);
            uint32_t dstB = smem_u32(&Bs[ch * ST_BYTES + row * CHKB + seg]);
            cp_async16(dstA, &g_znq[(size_t)(r0 + row) * D + ch * 128 + seg]);
            cp_async16(dstB, &g_znq[(size_t)(c0 + row) * D + ch * 128 + seg]);
        }
        CP_COMMIT();
    };

    issue_chunk(0);
    issue_chunk(1);

    const int warp_m = wid & 3;
    const int warp_n = wid >> 2;

    // per-lane ldmatrix base addresses (stage 0), byte offsets
    uint32_t aAddr[2];
    #pragma unroll
    for (int mf = 0; mf < 2; mf++) {
        int row  = warp_m * 32 + mf * 16 + (lid & 15);
        int colb = (lid >> 4) << 4;             // 0 or 16
        aAddr[mf] = smem_u32(&As[row * CHKB + colb]);
    }
    uint32_t bAddr[4];
    #pragma unroll
    for (int nq = 0; nq < 4; nq++) {
        int row  = warp_n * 64 + nq * 16 + ((lid >> 4) << 3) + (lid & 7);
        int colb = (lid & 8) << 1;              // 0 or 16
        bAddr[nq] = smem_u32(&Bs[row * CHKB + colb]);
    }

    int acc[2][8][4];
    #pragma unroll
    for (int i = 0; i < 2; i++)
        #pragma unroll
        for (int j = 0; j < 8; j++)
            #pragma unroll
            for (int e = 0; e < 4; e++) acc[i][j][e] = 0;

    #pragma unroll
    for (int ch = 0; ch < 2; ch++) {
        if (ch == 0) CP_WAIT(1); else CP_WAIT(0);
        __syncthreads();
        const uint32_t cb = (uint32_t)ch * ST_BYTES;
        #pragma unroll
        for (int ks = 0; ks < 4; ks++) {          // 4 k-steps of 32 per chunk
            const uint32_t kb = cb + ks * 32;
            uint32_t a[2][4], b[4][4];
            #pragma unroll
            for (int mf = 0; mf < 2; mf++)
                asm volatile("ldmatrix.sync.aligned.m8n8.x4.shared.b16 {%0,%1,%2,%3}, [%4];"
                             : "=r"(a[mf][0]), "=r"(a[mf][1]), "=r"(a[mf][2]), "=r"(a[mf][3])
                             : "r"(aAddr[mf] + kb));
            #pragma unroll
            for (int nq = 0; nq < 4; nq++)
                asm volatile("ldmatrix.sync.aligned.m8n8.x4.shared.b16 {%0,%1,%2,%3}, [%4];"
                             : "=r"(b[nq][0]), "=r"(b[nq][1]), "=r"(b[nq][2]), "=r"(b[nq][3])
                             : "r"(bAddr[nq] + kb));
            #pragma unroll
            for (int mf = 0; mf < 2; mf++)
                #pragma unroll
                for (int nf = 0; nf < 8; nf++) {
                    const int nq = nf >> 1, base = (nf & 1) * 2;
                    asm volatile(
                        "mma.sync.aligned.m16n8k32.row.col.s32.s8.s8.s32 "
                        "{%0,%1,%2,%3}, {%4,%5,%6,%7}, {%8,%9}, {%0,%1,%2,%3};"
                        : "+r"(acc[mf][nf][0]), "+r"(acc[mf][nf][1]),
                          "+r"(acc[mf][nf][2]), "+r"(acc[mf][nf][3])
                        : "r"(a[mf][0]), "r"(a[mf][1]), "r"(a[mf][2]), "r"(a[mf][3]),
                          "r"(b[nq][base]), "r"(b[nq][base + 1]));
                }
        }
        // no trailing __syncthreads: each buffer is filled once, never reused
    }

    // -----------------------------------------------------------------------
    // Epilogue. exp(sim-2) = ex2(acc*C1 + C0) on the MUFU pipe. Off-diag:
    // accumulate into row sums AND column sums (mirror tile). Diag: row sums
    // only, mask c==r. One pos write covers (r,c) and (c,r).
    // -----------------------------------------------------------------------
    const float SC = 2.0f / 16129.0f;   // 2 / 127^2 (for pos sim values)
    const int qrow = lid >> 2, qcol = lid & 3;
    const bool has_pos = (by == bx + (B / TILE));
    float rs[4] = {0.f, 0.f, 0.f, 0.f};
    float cs[8][2];
    #pragma unroll
    for (int nf = 0; nf < 8; nf++) { cs[nf][0] = 0.f; cs[nf][1] = 0.f; }

    #pragma unroll
    for (int mf = 0; mf < 2; mf++) {
        #pragma unroll
        for (int sub = 0; sub < 2; sub++) {
            const int r = r0 + warp_m * 32 + mf * 16 + sub * 8 + qrow;
            const int partner = (r < B) ? (r + B) : (r - B);
            #pragma unroll
            for (int nf = 0; nf < 8; nf++) {
                #pragma unroll
                for (int e = 0; e < 2; e++) {
                    const int c = c0 + warp_n * 64 + nf * 8 + qcol * 2 + e;
                    const int av = acc[mf][nf][sub * 2 + e];
                    float ex = exp2_mufu(fmaf((float)av, EXP_C1, EXP_C0));
                    if (diag && c == r) ex = 0.0f;
                    rs[mf * 2 + sub] += ex;
                    if (!diag) cs[nf][e] += ex;
                    if (has_pos && c == partner) {
                        const float sim = SC * (float)av;
                        g_pos[r] = sim; g_pos[c] = sim;
                    }
                }
            }
        }
    }

    // row sums: reduce across qcol (lanes 1,2)
    #pragma unroll
    for (int i = 0; i < 4; i++) {
        rs[i] += __shfl_xor_sync(0xffffffffu, rs[i], 1);
        rs[i] += __shfl_xor_sync(0xffffffffu, rs[i], 2);
    }
    if (qcol == 0) {
        #pragma unroll
        for (int mf = 0; mf < 2; mf++)
            #pragma unroll
            for (int sub = 0; sub < 2; sub++) {
                const int r = r0 + warp_m * 32 + mf * 16 + sub * 8 + qrow;
                atomicAdd(&g_S[r], rs[mf * 2 + sub]);
            }
    }

    // col sums: reduce across qrow (lanes 4,8,16); lanes 0..3 write
    if (!diag) {
        #pragma unroll
        for (int nf = 0; nf < 8; nf++) {
            #pragma unroll
            for (int e = 0; e < 2; e++) {
                float v = cs[nf][e];
                v += __shfl_xor_sync(0xffffffffu, v, 4);
                v += __shfl_xor_sync(0xffffffffu, v, 8);
                v += __shfl_xor_sync(0xffffffffu, v, 16);
                if (lid < 4) {
                    const int c = c0 + warp_n * 64 + nf * 8 + qcol * 2 + e;
                    atomicAdd(&g_S[c], v);
                }
            }
        }
    }
}

// ---------------------------------------------------------------------------
// Kernel 3: loss = (1/N) * sum_i (2 + log(S_i) - pos_i)
// ---------------------------------------------------------------------------
__global__ void k_final(float* __restrict__ out, int Nn) {
    int t = threadIdx.x;
    float s = 0.0f;
    for (int i = t; i < Nn; i += 1024)
        s += 2.0f + logf(g_S[i]) - g_pos[i];
    #pragma unroll
    for (int o = 16; o > 0; o >>= 1) s += __shfl_xor_sync(0xffffffffu, s, o);
    __shared__ float ws[32];
    if ((t & 31) == 0) ws[t >> 5] = s;
    __syncthreads();
    if (t < 32) {
        float x = ws[t];
        #pragma unroll
        for (int o = 16; o > 0; o >>= 1) x += __shfl_xor_sync(0xffffffffu, x, o);
        if (t == 0) out[0] = x / (float)Nn;
    }
}

// ---------------------------------------------------------------------------
extern "C" void kernel_launch(void* const* d_in, const int* in_sizes, int n_in,
                              void* d_out, int out_size) {
    const float* zi = (const float*)d_in[0];
    const float* zj = (const float*)d_in[1];
    int B  = in_sizes[0] / D;   // 4096
    int Nn = 2 * B;             // 8192

    const int smem_bytes = 4 * ST_BYTES;   // 73728
    cudaFuncSetAttribute(k_simgemm_sym,
                         cudaFuncAttributeMaxDynamicSharedMemorySize, smem_bytes);

    k_normalize<<<Nn / 8, 256>>>(zi, zj, B);
    const int ntiles = Nn / TILE;                  // 64
    const int nblocks = ntiles * (ntiles + 1) / 2; // 2080
    k_simgemm_sym<<<nblocks, 256, smem_bytes>>>(Nn, B);
    k_final<<<1, 1024>>>((float*)d_out, Nn);
}